// round 1
// baseline (speedup 1.0000x reference)
#include <cuda_runtime.h>
#include <mma.h>
#include <math.h>

using namespace nvcuda;

// Problem constants
#define BATCH   1024
#define SEQ     96
#define INSZ    128
#define HID     1024
#define G4      4096     // 4*HID
#define HORIZON 24
#define OUTSZ   128

// GEMM tiling
#define BM 128
#define BN 128
#define BK 32
#define KPAD 4           // smem row stride = 36 floats = 144B (16B aligned)

// ---------------------------------------------------------------------------
// Scratch (device globals; no allocation allowed)
// ---------------------------------------------------------------------------
__device__ __align__(16) float g_Gx[(size_t)SEQ * BATCH * G4]; // 1.61 GB: per-t gate pre-activations (x-part), later overwritten with full gates
__device__ __align__(16) float g_Gd[(size_t)BATCH * G4];       // decoder gate buffer
__device__ __align__(16) float g_h [(size_t)BATCH * HID];
__device__ __align__(16) float g_c [(size_t)BATCH * HID];
__device__ __align__(16) float g_hd[(size_t)BATCH * HID];
__device__ __align__(16) float g_cd[(size_t)BATCH * HID];

// ---------------------------------------------------------------------------
// Generic NT GEMM: C[M,N] (+)= A[M,K] @ B[N,K]^T   (tf32 inputs, fp32 accum)
// If C_INIT: accumulators are initialized from C (so bias/addend can be
// pre-staged in C); else zero-init.
// All of M,N divisible by 128; K divisible by 32.
// ---------------------------------------------------------------------------
template <bool C_INIT>
__global__ void __launch_bounds__(256)
gemm_nt(const float* __restrict__ A, const float* __restrict__ B,
        float* __restrict__ C,
        int M, int N, int K, int lda, int ldb, int ldc)
{
    __shared__ __align__(16) float As[BM][BK + KPAD];
    __shared__ __align__(16) float Bs[BN][BK + KPAD];

    const int m0  = blockIdx.y * BM;
    const int n0  = blockIdx.x * BN;
    const int tid = threadIdx.x;
    const int wid = tid >> 5;
    const int wm  = wid & 3;   // 4 warps along M -> 32 rows each
    const int wn  = wid >> 2;  // 2 warps along N -> 64 cols each

    wmma::fragment<wmma::accumulator, 16, 16, 8, float> acc[2][4];

    if (C_INIT) {
        #pragma unroll
        for (int mi = 0; mi < 2; mi++)
            #pragma unroll
            for (int ni = 0; ni < 4; ni++)
                wmma::load_matrix_sync(acc[mi][ni],
                    C + (size_t)(m0 + wm * 32 + mi * 16) * (size_t)ldc
                      + n0 + wn * 64 + ni * 16,
                    ldc, wmma::mem_row_major);
    } else {
        #pragma unroll
        for (int mi = 0; mi < 2; mi++)
            #pragma unroll
            for (int ni = 0; ni < 4; ni++)
                wmma::fill_fragment(acc[mi][ni], 0.0f);
    }

    for (int k0 = 0; k0 < K; k0 += BK) {
        // Cooperative tile load: 256 threads x 4 float4 each per matrix
        #pragma unroll
        for (int i = 0; i < 4; i++) {
            int q  = tid + i * 256;       // 0..1023 float4 slots
            int r  = q >> 3;              // row within tile (8 float4 per row)
            int c4 = q & 7;
            float4 av = *(const float4*)(A + (size_t)(m0 + r) * (size_t)lda + k0 + c4 * 4);
            *(float4*)&As[r][c4 * 4] = av;
            float4 bv = *(const float4*)(B + (size_t)(n0 + r) * (size_t)ldb + k0 + c4 * 4);
            *(float4*)&Bs[r][c4 * 4] = bv;
        }
        __syncthreads();

        #pragma unroll
        for (int ks = 0; ks < BK / 8; ks++) {
            wmma::fragment<wmma::matrix_a, 16, 16, 8, wmma::precision::tf32, wmma::row_major> af[2];
            wmma::fragment<wmma::matrix_b, 16, 16, 8, wmma::precision::tf32, wmma::col_major> bf[4];
            #pragma unroll
            for (int mi = 0; mi < 2; mi++) {
                wmma::load_matrix_sync(af[mi], &As[wm * 32 + mi * 16][ks * 8], BK + KPAD);
                #pragma unroll
                for (int t = 0; t < af[mi].num_elements; t++)
                    af[mi].x[t] = wmma::__float_to_tf32(af[mi].x[t]);
            }
            #pragma unroll
            for (int ni = 0; ni < 4; ni++) {
                wmma::load_matrix_sync(bf[ni], &Bs[wn * 64 + ni * 16][ks * 8], BK + KPAD);
                #pragma unroll
                for (int t = 0; t < bf[ni].num_elements; t++)
                    bf[ni].x[t] = wmma::__float_to_tf32(bf[ni].x[t]);
            }
            #pragma unroll
            for (int mi = 0; mi < 2; mi++)
                #pragma unroll
                for (int ni = 0; ni < 4; ni++)
                    wmma::mma_sync(acc[mi][ni], af[mi], bf[ni], acc[mi][ni]);
        }
        __syncthreads();
    }

    #pragma unroll
    for (int mi = 0; mi < 2; mi++)
        #pragma unroll
        for (int ni = 0; ni < 4; ni++)
            wmma::store_matrix_sync(
                C + (size_t)(m0 + wm * 32 + mi * 16) * (size_t)ldc
                  + n0 + wn * 64 + ni * 16,
                acc[mi][ni], ldc, wmma::mem_row_major);
}

// ---------------------------------------------------------------------------
// Elementwise LSTM cell update. Gates laid out [i, f, g, o] blocks of HID.
// G row for batch b lives at G + (size_t)b * grs. Biases added here.
// ---------------------------------------------------------------------------
__global__ void lstm_elem(const float* __restrict__ G, long grs,
                          const float* __restrict__ b1, const float* __restrict__ b2,
                          float* __restrict__ h, float* __restrict__ c, int first)
{
    int tid = blockIdx.x * blockDim.x + threadIdx.x;  // [0, BATCH*HID)
    int b = tid >> 10;
    int j = tid & 1023;
    size_t base = (size_t)b * (size_t)grs;

    float ip = G[base + j]            + b1[j]            + b2[j];
    float fp = G[base + HID + j]      + b1[HID + j]      + b2[HID + j];
    float gp = G[base + 2 * HID + j]  + b1[2 * HID + j]  + b2[2 * HID + j];
    float op = G[base + 3 * HID + j]  + b1[3 * HID + j]  + b2[3 * HID + j];

    float cold = first ? 0.0f : c[tid];
    float si = 1.0f / (1.0f + expf(-ip));
    float sf = 1.0f / (1.0f + expf(-fp));
    float so = 1.0f / (1.0f + expf(-op));
    float cn = sf * cold + si * tanhf(gp);
    c[tid] = cn;
    h[tid] = so * tanhf(cn);
}

// Broadcast a bias vector into a buffer: dst[i] = bias[i % n]
__global__ void fill_bias(float* __restrict__ dst, const float* __restrict__ bias,
                          int n, size_t total)
{
    size_t i = (size_t)blockIdx.x * blockDim.x + threadIdx.x;
    if (i < total) dst[i] = bias[i % n];
}

// ---------------------------------------------------------------------------
// Launch sequence (graph-capturable: kernels only)
// ---------------------------------------------------------------------------
extern "C" void kernel_launch(void* const* d_in, const int* in_sizes, int n_in,
                              void* d_out, int out_size)
{
    const float* x      = (const float*)d_in[0];
    const float* W_ih_e = (const float*)d_in[1];
    const float* W_hh_e = (const float*)d_in[2];
    const float* b_ih_e = (const float*)d_in[3];
    const float* b_hh_e = (const float*)d_in[4];
    const float* W_ih_d = (const float*)d_in[5];
    const float* W_hh_d = (const float*)d_in[6];
    const float* b_ih_d = (const float*)d_in[7];
    const float* b_hh_d = (const float*)d_in[8];
    const float* W_fc   = (const float*)d_in[9];
    const float* b_fc   = (const float*)d_in[10];
    const float* W_fcc  = (const float*)d_in[11];
    const float* b_fcc  = (const float*)d_in[12];
    const float* W_out  = (const float*)d_in[13];
    const float* b_out  = (const float*)d_in[14];
    float* out = (float*)d_out;

    float *Gx, *Gd, *h, *c, *hd, *cd;
    cudaGetSymbolAddress((void**)&Gx, g_Gx);
    cudaGetSymbolAddress((void**)&Gd, g_Gd);
    cudaGetSymbolAddress((void**)&h,  g_h);
    cudaGetSymbolAddress((void**)&c,  g_c);
    cudaGetSymbolAddress((void**)&hd, g_hd);
    cudaGetSymbolAddress((void**)&cd, g_cd);

    const long LDGX = (long)SEQ * G4;  // 393216: Gx row stride between batches

    // 1) Hoisted input GEMM for ALL encoder timesteps:
    //    Gx[(b*SEQ+t), :] = x[b,t,:] @ W_ih_e^T     (M=98304, N=4096, K=128)
    gemm_nt<false><<<dim3(G4 / BN, (BATCH * SEQ) / BM), 256>>>(
        x, W_ih_e, Gx, BATCH * SEQ, G4, INSZ, INSZ, INSZ, G4);

    // 2) Pre-stage biases into C buffers used with C_INIT GEMMs
    fill_bias<<<(BATCH * HID + 255) / 256, 256>>>(hd, b_fc,  HID, (size_t)BATCH * HID);
    fill_bias<<<(BATCH * HID + 255) / 256, 256>>>(cd, b_fcc, HID, (size_t)BATCH * HID);
    fill_bias<<<(BATCH * HORIZON * OUTSZ + 255) / 256, 256>>>(
        out, b_out, OUTSZ, (size_t)BATCH * HORIZON * OUTSZ);

    // 3) Encoder: 96 steps. Step-GEMM accumulates h@W_hh^T on top of Gx[t].
    for (int t = 0; t < SEQ; t++) {
        if (t > 0) {
            gemm_nt<true><<<dim3(G4 / BN, BATCH / BM), 256>>>(
                h, W_hh_e, Gx + (size_t)t * G4,
                BATCH, G4, HID, HID, HID, (int)LDGX);
        }
        lstm_elem<<<(BATCH * HID) / 256, 256>>>(
            Gx + (size_t)t * G4, LDGX, b_ih_e, b_hh_e, h, c, t == 0);
    }

    // 4) Bridge: h_dec = h@W_fc^T + b_fc ; c_dec = h@W_fcc^T + b_fcc
    gemm_nt<true><<<dim3(HID / BN, BATCH / BM), 256>>>(
        h, W_fc,  hd, BATCH, HID, HID, HID, HID, HID);
    gemm_nt<true><<<dim3(HID / BN, BATCH / BM), 256>>>(
        h, W_fcc, cd, BATCH, HID, HID, HID, HID, HID);

    // 5) Decoder: 24 autoregressive steps
    for (int t = 0; t < HORIZON; t++) {
        // Gd = h_dec @ W_hh_d^T
        gemm_nt<false><<<dim3(G4 / BN, BATCH / BM), 256>>>(
            hd, W_hh_d, Gd, BATCH, G4, HID, HID, HID, G4);
        // Gd += out[:, t-1, :] @ W_ih_d^T   (decoder input; zero at t=0)
        if (t > 0) {
            gemm_nt<true><<<dim3(G4 / BN, BATCH / BM), 256>>>(
                out + (size_t)(t - 1) * OUTSZ, W_ih_d, Gd,
                BATCH, G4, OUTSZ, HORIZON * OUTSZ, OUTSZ, G4);
        }
        lstm_elem<<<(BATCH * HID) / 256, 256>>>(
            Gd, G4, b_ih_d, b_hh_d, hd, cd, 0);
        // out[:, t, :] = h_dec @ W_out^T + b_out (bias pre-staged in out)
        gemm_nt<true><<<dim3(OUTSZ / BN, BATCH / BM), 256>>>(
            hd, W_out, out + (size_t)t * OUTSZ,
            BATCH, OUTSZ, HID, HID, HID, HORIZON * OUTSZ);
    }
}

// round 2
// speedup vs baseline: 2.2668x; 2.2668x over previous
#include <cuda_runtime.h>
#include <cstdint>
#include <math.h>

#define BATCH   1024
#define SEQ     96
#define INSZ    128
#define HID     1024
#define G4      4096
#define HORIZON 24
#define OUTSZ   128
#define KCAT    1152   // 1024 + 128

#define BM      128
#define BK      32
#define SMS     36     // smem row stride in floats (conflict-free: 36r+c -> 4r+c mod 32)

// ---------------------------------------------------------------------------
// Scratch (device globals; allocation is forbidden)
// ---------------------------------------------------------------------------
__device__ __align__(16) float g_h   [2 * BATCH * HID];   // encoder h ping-pong
__device__ __align__(16) float g_c   [BATCH * HID];       // encoder c (in-place)
__device__ __align__(16) float g_hcat[2 * BATCH * KCAT];  // decoder [h | out_prev] ping-pong
__device__ __align__(16) float g_cd  [BATCH * HID];       // decoder c
__device__ __align__(16) float g_We  [G4 * KCAT];         // gate-interleaved [W_hh_e | W_ih_e]
__device__ __align__(16) float g_Wd  [G4 * KCAT];         // gate-interleaved [W_hh_d | W_ih_d]
__device__ __align__(16) float g_be  [G4];                // interleaved b_ih_e + b_hh_e
__device__ __align__(16) float g_bd  [G4];

// ---------------------------------------------------------------------------
// Small helpers
// ---------------------------------------------------------------------------
__device__ __forceinline__ uint32_t f2tf(float f) {
    uint32_t r; asm("cvt.rna.tf32.f32 %0, %1;" : "=r"(r) : "f"(f)); return r;
}
__device__ __forceinline__ void mma_tf32(float* c, const uint32_t* a, const uint32_t* b) {
    asm volatile(
        "mma.sync.aligned.m16n8k8.row.col.f32.tf32.tf32.f32 "
        "{%0,%1,%2,%3}, {%4,%5,%6,%7}, {%8,%9}, {%0,%1,%2,%3};"
        : "+f"(c[0]), "+f"(c[1]), "+f"(c[2]), "+f"(c[3])
        : "r"(a[0]), "r"(a[1]), "r"(a[2]), "r"(a[3]), "r"(b[0]), "r"(b[1]));
}
__device__ __forceinline__ void cp16(float* smem, const float* g) {
    uint32_t s = (uint32_t)__cvta_generic_to_shared(smem);
    asm volatile("cp.async.cg.shared.global [%0], [%1], 16;" :: "r"(s), "l"(g));
}
__device__ __forceinline__ float fsig(float x) {
    return __fdividef(1.0f, 1.0f + __expf(-x));
}
__device__ __forceinline__ float ftanh(float x) {
    return __fdividef(2.0f, 1.0f + __expf(-2.0f * x)) - 1.0f;
}

// ---------------------------------------------------------------------------
// Weight prep: Wcat[4j+g][0:1024]   = W_hh[g*1024+j][:]
//              Wcat[4j+g][1024:1152]= W_ih[g*1024+j][:]
//              bcat[4j+g] = b_ih[g*1024+j] + b_hh[g*1024+j]
// ---------------------------------------------------------------------------
__global__ void prep_w(const float* __restrict__ Whh, const float* __restrict__ Wih,
                       const float* __restrict__ b1, const float* __restrict__ b2,
                       float* __restrict__ Wcat, float* __restrict__ bcat)
{
    long idx = (long)blockIdx.x * blockDim.x + threadIdx.x;
    if (idx >= (long)G4 * KCAT) return;
    int row = (int)(idx / KCAT);
    int k   = (int)(idx % KCAT);
    int j = row >> 2, g = row & 3;
    int orow = g * HID + j;
    Wcat[idx] = (k < HID) ? Whh[(size_t)orow * HID + k]
                          : Wih[(size_t)orow * INSZ + (k - HID)];
    if (k == 0) bcat[row] = b1[orow] + b2[orow];
}

// ---------------------------------------------------------------------------
// Core GEMM: C[M=grid.y*128, N=grid.x*BN] = Acat @ B^T, tf32/fp32, cp.async
// 2-stage pipeline. K handled as 32-wide chunks [cb, ce); chunks < 32 read
// from A1 (lda1), chunks >= 32 read from A2 at k-1024 (lda2).
//
// LSTM=false: epilogue O1[r][c] = acc + bias[c]   (+ optional dual store O2)
// LSTM=true : gate-interleaved cols (c = 4j+g, g in {i,f,g~,o}).
//             Even-q lanes gather (g~,o) from lane^1 via shfl, compute
//             c_new = sig(f)*c_old + sig(i)*tanh(g~); h = sig(o)*tanh(c_new)
//             O1 = h (ldo1), O2 = c in/out (ldo2).
// ---------------------------------------------------------------------------
template<int BN, bool LSTM>
__global__ void __launch_bounds__(2 * BN)
gemm_k(const float* __restrict__ A1, int lda1,
       const float* __restrict__ A2, int lda2,
       const float* __restrict__ B,  int ldb,
       const float* __restrict__ bias,
       float* __restrict__ O1, int ldo1,
       float* __restrict__ O2, int ldo2,
       int cb, int ce, int first)
{
    constexpr int WN = BN / 64;      // warps along N
    constexpr int NT = 128 * WN;     // threads
    extern __shared__ float sm[];
    float* As = sm;                  // [2][BM][SMS]
    float* Bs = sm + 2 * BM * SMS;   // [2][BN][SMS]

    const int tid  = threadIdx.x;
    const int lane = tid & 31;
    const int wid  = tid >> 5;
    const int wm   = wid & 3;        // 4 warps along M (32 rows each)
    const int wn   = wid >> 2;       // WN warps along N (64 cols each)
    const int lr   = lane >> 2;
    const int lc   = lane & 3;
    const int m0   = blockIdx.y * BM;
    const int n0   = blockIdx.x * BN;

    float acc[2][8][4];
    #pragma unroll
    for (int mi = 0; mi < 2; mi++)
        #pragma unroll
        for (int nf = 0; nf < 8; nf++)
            #pragma unroll
            for (int t = 0; t < 4; t++) acc[mi][nf][t] = 0.0f;

    auto load_stage = [&](int st, int chunk) {
        float* as = As + st * BM * SMS;
        float* bs = Bs + st * BN * SMS;
        const int k0 = chunk * BK;
        #pragma unroll
        for (int i = 0; i < 1024 / NT; i++) {
            int q = tid + i * NT;
            int r = q >> 3, c4 = q & 7;
            const float* src = (chunk < 32)
                ? A1 + (size_t)(m0 + r) * lda1 + k0 + c4 * 4
                : A2 + (size_t)(m0 + r) * lda2 + (k0 - HID) + c4 * 4;
            cp16(as + r * SMS + c4 * 4, src);
        }
        #pragma unroll
        for (int i = 0; i < BN * 8 / NT; i++) {
            int q = tid + i * NT;
            int r = q >> 3, c4 = q & 7;
            cp16(bs + r * SMS + c4 * 4,
                 B + (size_t)(n0 + r) * ldb + k0 + c4 * 4);
        }
        asm volatile("cp.async.commit_group;");
    };

    load_stage(0, cb);
    for (int ch = cb; ch < ce; ch++) {
        int st = (ch - cb) & 1;
        if (ch + 1 < ce) {
            load_stage(st ^ 1, ch + 1);
            asm volatile("cp.async.wait_group 1;");
        } else {
            asm volatile("cp.async.wait_group 0;");
        }
        __syncthreads();

        const float* as = As + st * BM * SMS + (wm * 32) * SMS;
        const float* bs = Bs + st * BN * SMS + (wn * 64) * SMS;
        #pragma unroll
        for (int ks = 0; ks < 4; ks++) {
            const int kk = ks * 8;
            uint32_t af[2][4];
            #pragma unroll
            for (int mi = 0; mi < 2; mi++) {
                const float* ap = as + (mi * 16 + lr) * SMS + kk + lc;
                af[mi][0] = f2tf(ap[0]);
                af[mi][1] = f2tf(ap[8 * SMS]);
                af[mi][2] = f2tf(ap[4]);
                af[mi][3] = f2tf(ap[8 * SMS + 4]);
            }
            #pragma unroll
            for (int nf = 0; nf < 8; nf++) {
                const float* bp = bs + (nf * 8 + lr) * SMS + kk + lc;
                uint32_t bf[2];
                bf[0] = f2tf(bp[0]);
                bf[1] = f2tf(bp[4]);
                #pragma unroll
                for (int mi = 0; mi < 2; mi++)
                    mma_tf32(acc[mi][nf], af[mi], bf);
            }
        }
        __syncthreads();
    }

    const int rb = m0 + wm * 32 + lr;
    if (!LSTM) {
        #pragma unroll
        for (int mi = 0; mi < 2; mi++) {
            #pragma unroll
            for (int nf = 0; nf < 8; nf++) {
                int cg = n0 + wn * 64 + nf * 8 + 2 * lc;
                float b0 = bias ? bias[cg] : 0.0f;
                float b1 = bias ? bias[cg + 1] : 0.0f;
                int r0 = rb + mi * 16, r1 = r0 + 8;
                float2 v0 = make_float2(acc[mi][nf][0] + b0, acc[mi][nf][1] + b1);
                float2 v1 = make_float2(acc[mi][nf][2] + b0, acc[mi][nf][3] + b1);
                *(float2*)&O1[(size_t)r0 * ldo1 + cg] = v0;
                *(float2*)&O1[(size_t)r1 * ldo1 + cg] = v1;
                if (O2) {
                    *(float2*)&O2[(size_t)r0 * ldo2 + cg] = v0;
                    *(float2*)&O2[(size_t)r1 * ldo2 + cg] = v1;
                }
            }
        }
    } else {
        #pragma unroll
        for (int mi = 0; mi < 2; mi++) {
            #pragma unroll
            for (int nf = 0; nf < 8; nf++) {
                int cg = n0 + wn * 64 + nf * 8 + 2 * lc;   // = 4j+g (even)
                float v0 = acc[mi][nf][0] + bias[cg];
                float v1 = acc[mi][nf][1] + bias[cg + 1];
                float v2 = acc[mi][nf][2] + bias[cg];
                float v3 = acc[mi][nf][3] + bias[cg + 1];
                float p0 = __shfl_xor_sync(0xffffffffu, v0, 1);
                float p1 = __shfl_xor_sync(0xffffffffu, v1, 1);
                float p2 = __shfl_xor_sync(0xffffffffu, v2, 1);
                float p3 = __shfl_xor_sync(0xffffffffu, v3, 1);
                if ((lane & 1) == 0) {
                    // this lane holds (i,f) pre-acts; partner holds (g~,o)
                    int j  = cg >> 2;
                    int r0 = rb + mi * 16, r1 = r0 + 8;
                    {
                        float i_ = fsig(v0), f_ = fsig(v1);
                        float g_ = ftanh(p0), o_ = fsig(p1);
                        float co = first ? 0.0f : O2[(size_t)r0 * ldo2 + j];
                        float cn = f_ * co + i_ * g_;
                        O2[(size_t)r0 * ldo2 + j] = cn;
                        O1[(size_t)r0 * ldo1 + j] = o_ * ftanh(cn);
                    }
                    {
                        float i_ = fsig(v2), f_ = fsig(v3);
                        float g_ = ftanh(p2), o_ = fsig(p3);
                        float co = first ? 0.0f : O2[(size_t)r1 * ldo2 + j];
                        float cn = f_ * co + i_ * g_;
                        O2[(size_t)r1 * ldo2 + j] = cn;
                        O1[(size_t)r1 * ldo1 + j] = o_ * ftanh(cn);
                    }
                }
            }
        }
    }
}

// ---------------------------------------------------------------------------
// Launch sequence (graph-capturable: kernel launches only)
// ---------------------------------------------------------------------------
extern "C" void kernel_launch(void* const* d_in, const int* in_sizes, int n_in,
                              void* d_out, int out_size)
{
    const float* x      = (const float*)d_in[0];
    const float* W_ih_e = (const float*)d_in[1];
    const float* W_hh_e = (const float*)d_in[2];
    const float* b_ih_e = (const float*)d_in[3];
    const float* b_hh_e = (const float*)d_in[4];
    const float* W_ih_d = (const float*)d_in[5];
    const float* W_hh_d = (const float*)d_in[6];
    const float* b_ih_d = (const float*)d_in[7];
    const float* b_hh_d = (const float*)d_in[8];
    const float* W_fc   = (const float*)d_in[9];
    const float* b_fc   = (const float*)d_in[10];
    const float* W_fcc  = (const float*)d_in[11];
    const float* b_fcc  = (const float*)d_in[12];
    const float* W_out  = (const float*)d_in[13];
    const float* b_out  = (const float*)d_in[14];
    float* out = (float*)d_out;

    float *h, *c, *hcat, *cd, *We, *Wd, *be, *bd;
    cudaGetSymbolAddress((void**)&h,    g_h);
    cudaGetSymbolAddress((void**)&c,    g_c);
    cudaGetSymbolAddress((void**)&hcat, g_hcat);
    cudaGetSymbolAddress((void**)&cd,   g_cd);
    cudaGetSymbolAddress((void**)&We,   g_We);
    cudaGetSymbolAddress((void**)&Wd,   g_Wd);
    cudaGetSymbolAddress((void**)&be,   g_be);
    cudaGetSymbolAddress((void**)&bd,   g_bd);

    const int SMEM_L = 2 * (BM + 256) * SMS * 4;  // 110,592 B (BN=256)
    const int SMEM_P = 2 * (BM + 128) * SMS * 4;  //  73,728 B (BN=128)
    static bool attr_done = false;
    cudaFuncSetAttribute(gemm_k<256, true>,  cudaFuncAttributeMaxDynamicSharedMemorySize, SMEM_L);
    cudaFuncSetAttribute(gemm_k<128, false>, cudaFuncAttributeMaxDynamicSharedMemorySize, SMEM_P);
    (void)attr_done;

    // ---- weight prep (runs every launch; deterministic) ----
    {
        long total = (long)G4 * KCAT;
        int blocks = (int)((total + 255) / 256);
        prep_w<<<blocks, 256>>>(W_hh_e, W_ih_e, b_ih_e, b_hh_e, We, be);
        prep_w<<<blocks, 256>>>(W_hh_d, W_ih_d, b_ih_d, b_hh_d, Wd, bd);
    }

    const dim3 gL(G4 / 256, BATCH / BM);    // (16, 8) — 128 CTAs, single wave
    const dim3 gB(HID / 128, BATCH / BM);   // (8, 8)
    const dim3 gO(OUTSZ / 128, BATCH / BM); // (1, 8)

    // ---- encoder: 96 fused GEMM+LSTM steps ----
    int p = 0;
    for (int t = 0; t < SEQ; t++) {
        // A = [h_prev | x_t]; t==0 skips the h part (h_prev = 0) via cb=32
        gemm_k<256, true><<<gL, 512, SMEM_L>>>(
            h + (size_t)p * BATCH * HID, HID,
            x + (size_t)t * INSZ, SEQ * INSZ,
            We, KCAT, be,
            h + (size_t)(1 - p) * BATCH * HID, HID,
            c, HID,
            (t == 0) ? 32 : 0, 36, (t == 0) ? 1 : 0);
        p ^= 1;
    }
    float* h_fin = h + (size_t)p * BATCH * HID;

    // ---- bridge ----
    float* hc0 = hcat;                          // decoder ping buffer
    float* hc1 = hcat + (size_t)BATCH * KCAT;   // pong
    gemm_k<128, false><<<gB, 256, SMEM_P>>>(
        h_fin, HID, nullptr, 0, W_fc, HID, b_fc,
        hc0, KCAT, nullptr, 0, 0, 32, 0);
    gemm_k<128, false><<<gB, 256, SMEM_P>>>(
        h_fin, HID, nullptr, 0, W_fcc, HID, b_fcc,
        cd, HID, nullptr, 0, 0, 32, 0);

    // ---- decoder: 24 steps (fused GEMM+LSTM, then out-proj w/ dual store) ----
    int q = 0;
    for (int t = 0; t < HORIZON; t++) {
        float* src = (q == 0) ? hc0 : hc1;
        float* dst = (q == 0) ? hc1 : hc0;
        // A = [h_dec | out_prev]; t==0 has out_prev = 0 -> ce=32 (K=1024 only)
        gemm_k<256, true><<<gL, 512, SMEM_L>>>(
            src, KCAT, src + HID, KCAT,
            Wd, KCAT, bd,
            dst, KCAT,
            cd, HID,
            0, (t == 0) ? 32 : 36, 0);
        // out[:, t, :] = h_dec @ W_out^T + b_out; also stage into dst[:,1024:]
        gemm_k<128, false><<<gO, 256, SMEM_P>>>(
            dst, KCAT, nullptr, 0, W_out, HID, b_out,
            out + (size_t)t * OUTSZ, HORIZON * OUTSZ,
            dst + HID, KCAT, 0, 32, 0);
        q ^= 1;
    }
}

// round 3
// speedup vs baseline: 2.6069x; 1.1500x over previous
#include <cuda_runtime.h>
#include <cstdint>
#include <math.h>

#define BATCH   1024
#define SEQ     96
#define INSZ    128
#define HID     1024
#define G4      4096
#define HORIZON 24
#define OUTSZ   128
#define KCAT    1152   // 1024 + 128

#define BK      32
#define SMS     36     // smem row stride in floats (conflict-free)
#define STAGES  3

// ---------------------------------------------------------------------------
// Scratch (device globals; allocation is forbidden)
// ---------------------------------------------------------------------------
__device__ __align__(16) float g_h   [2 * BATCH * HID];   // encoder h ping-pong
__device__ __align__(16) float g_c   [BATCH * HID];       // encoder c (in-place)
__device__ __align__(16) float g_hcat[2 * BATCH * KCAT];  // decoder [h | out_prev] ping-pong
__device__ __align__(16) float g_cd  [BATCH * HID];       // decoder c
__device__ __align__(16) float g_We  [G4 * KCAT];         // gate-interleaved [W_hh_e | W_ih_e], tf32-rounded
__device__ __align__(16) float g_Wd  [G4 * KCAT];
__device__ __align__(16) float g_be  [G4];
__device__ __align__(16) float g_bd  [G4];

// ---------------------------------------------------------------------------
// Helpers
// ---------------------------------------------------------------------------
__device__ __forceinline__ float tf32_rna(float f) {
    uint32_t r; asm("cvt.rna.tf32.f32 %0, %1;" : "=r"(r) : "f"(f));
    return __uint_as_float(r);
}
__device__ __forceinline__ void mma_tf32(float* c, const uint32_t* a, const uint32_t* b) {
    asm volatile(
        "mma.sync.aligned.m16n8k8.row.col.f32.tf32.tf32.f32 "
        "{%0,%1,%2,%3}, {%4,%5,%6,%7}, {%8,%9}, {%0,%1,%2,%3};"
        : "+f"(c[0]), "+f"(c[1]), "+f"(c[2]), "+f"(c[3])
        : "r"(a[0]), "r"(a[1]), "r"(a[2]), "r"(a[3]), "r"(b[0]), "r"(b[1]));
}
__device__ __forceinline__ void cp16(float* smem, const float* g) {
    uint32_t s = (uint32_t)__cvta_generic_to_shared(smem);
    asm volatile("cp.async.cg.shared.global [%0], [%1], 16;" :: "r"(s), "l"(g));
}
__device__ __forceinline__ float fsig(float x) {
    return __fdividef(1.0f, 1.0f + __expf(-x));
}
__device__ __forceinline__ float ftanh(float x) {
    return __fdividef(2.0f, 1.0f + __expf(-2.0f * x)) - 1.0f;
}

// ---------------------------------------------------------------------------
// Weight prep (gate-interleaved concat; tf32-RNA-rounded so the GEMM can use
// raw-bit truncation on activations only)
// ---------------------------------------------------------------------------
__global__ void prep_w(const float* __restrict__ Whh, const float* __restrict__ Wih,
                       const float* __restrict__ b1, const float* __restrict__ b2,
                       float* __restrict__ Wcat, float* __restrict__ bcat)
{
    long idx = (long)blockIdx.x * blockDim.x + threadIdx.x;
    if (idx >= (long)G4 * KCAT) return;
    int row = (int)(idx / KCAT);
    int k   = (int)(idx % KCAT);
    int j = row >> 2, g = row & 3;
    int orow = g * HID + j;
    float w = (k < HID) ? Whh[(size_t)orow * HID + k]
                        : Wih[(size_t)orow * INSZ + (k - HID)];
    Wcat[idx] = tf32_rna(w);
    if (k == 0) bcat[row] = b1[orow] + b2[orow];
}

// ---------------------------------------------------------------------------
// Core GEMM: C[M, N] = Acat @ B^T (tf32 via raw-bit truncation, fp32 accum).
// 3-stage cp.async pipeline, one __syncthreads per K-chunk.
// K chunks [cb, ce): chunk < 32 reads A1 (lda1); chunk >= 32 reads A2 (k-1024).
// Warp tile 32x64. LSTM epilogue as in round 2.
// ---------------------------------------------------------------------------
template<int TBM, int BN, bool LSTM>
__global__ void __launch_bounds__((TBM / 32) * (BN / 64) * 32)
gemm_k(const float* __restrict__ A1, int lda1,
       const float* __restrict__ A2, int lda2,
       const float* __restrict__ B,  int ldb,
       const float* __restrict__ bias,
       float* __restrict__ O1, int ldo1,
       float* __restrict__ O2, int ldo2,
       int cb, int ce, int first)
{
    constexpr int WM = TBM / 32;
    constexpr int WN = BN / 64;
    constexpr int NT = WM * WN * 32;
    constexpr int AS_ST = TBM * SMS;
    constexpr int BS_ST = BN * SMS;
    constexpr int IA = TBM * 8 / NT;   // A float4 granules per thread per stage
    constexpr int IB = BN * 8 / NT;

    extern __shared__ float sm[];
    float* As = sm;                     // [STAGES][TBM][SMS]
    float* Bs = sm + STAGES * AS_ST;    // [STAGES][BN][SMS]

    const int tid  = threadIdx.x;
    const int lane = tid & 31;
    const int wid  = tid >> 5;
    const int wm   = wid % WM;
    const int wn   = wid / WM;
    const int lr   = lane >> 2;
    const int lc   = lane & 3;
    const int m0   = blockIdx.y * TBM;
    const int n0   = blockIdx.x * BN;

    float acc[2][8][4];
    #pragma unroll
    for (int mi = 0; mi < 2; mi++)
        #pragma unroll
        for (int nf = 0; nf < 8; nf++)
            #pragma unroll
            for (int t = 0; t < 4; t++) acc[mi][nf][t] = 0.0f;

    auto load_stage = [&](int st, int chunk) {
        float* as = As + st * AS_ST;
        float* bs = Bs + st * BS_ST;
        const int k0 = chunk * BK;
        #pragma unroll
        for (int i = 0; i < IA; i++) {
            int q = tid + i * NT;
            int r = q >> 3, c4 = q & 7;
            const float* src = (chunk < 32)
                ? A1 + (size_t)(m0 + r) * lda1 + k0 + c4 * 4
                : A2 + (size_t)(m0 + r) * lda2 + (k0 - HID) + c4 * 4;
            cp16(as + r * SMS + c4 * 4, src);
        }
        #pragma unroll
        for (int i = 0; i < IB; i++) {
            int q = tid + i * NT;
            int r = q >> 3, c4 = q & 7;
            cp16(bs + r * SMS + c4 * 4,
                 B + (size_t)(n0 + r) * ldb + k0 + c4 * 4);
        }
    };

    // Prologue: stages for chunks cb, cb+1
    load_stage(0, cb);
    asm volatile("cp.async.commit_group;");
    if (cb + 1 < ce) load_stage(1, cb + 1);
    asm volatile("cp.async.commit_group;");

    for (int ch = cb; ch < ce; ch++) {
        const int it = ch - cb;
        asm volatile("cp.async.wait_group 1;");
        __syncthreads();

        // Issue next-stage loads (into the stage consumed 1 iter ago; safe
        // because every thread passed the sync above after consuming it).
        if (ch + 2 < ce) load_stage((it + 2) % STAGES, ch + 2);
        asm volatile("cp.async.commit_group;");

        const int st = it % STAGES;
        const float* as = As + st * AS_ST + (wm * 32) * SMS;
        const float* bs = Bs + st * BS_ST + (wn * 64) * SMS;
        #pragma unroll
        for (int ks = 0; ks < 4; ks++) {
            const int kk = ks * 8;
            uint32_t af[2][4];
            #pragma unroll
            for (int mi = 0; mi < 2; mi++) {
                const float* ap = as + (mi * 16 + lr) * SMS + kk + lc;
                af[mi][0] = __float_as_uint(ap[0]);
                af[mi][1] = __float_as_uint(ap[8 * SMS]);
                af[mi][2] = __float_as_uint(ap[4]);
                af[mi][3] = __float_as_uint(ap[8 * SMS + 4]);
            }
            #pragma unroll
            for (int nf = 0; nf < 8; nf++) {
                const float* bp = bs + (nf * 8 + lr) * SMS + kk + lc;
                uint32_t bf[2];
                bf[0] = __float_as_uint(bp[0]);
                bf[1] = __float_as_uint(bp[4]);
                #pragma unroll
                for (int mi = 0; mi < 2; mi++)
                    mma_tf32(acc[mi][nf], af[mi], bf);
            }
        }
        __syncthreads();
    }

    const int rb = m0 + wm * 32 + lr;
    if (!LSTM) {
        #pragma unroll
        for (int mi = 0; mi < 2; mi++) {
            #pragma unroll
            for (int nf = 0; nf < 8; nf++) {
                int cg = n0 + wn * 64 + nf * 8 + 2 * lc;
                float b0 = bias ? bias[cg] : 0.0f;
                float b1 = bias ? bias[cg + 1] : 0.0f;
                int r0 = rb + mi * 16, r1 = r0 + 8;
                float2 v0 = make_float2(acc[mi][nf][0] + b0, acc[mi][nf][1] + b1);
                float2 v1 = make_float2(acc[mi][nf][2] + b0, acc[mi][nf][3] + b1);
                *(float2*)&O1[(size_t)r0 * ldo1 + cg] = v0;
                *(float2*)&O1[(size_t)r1 * ldo1 + cg] = v1;
                if (O2) {
                    *(float2*)&O2[(size_t)r0 * ldo2 + cg] = v0;
                    *(float2*)&O2[(size_t)r1 * ldo2 + cg] = v1;
                }
            }
        }
    } else {
        #pragma unroll
        for (int mi = 0; mi < 2; mi++) {
            #pragma unroll
            for (int nf = 0; nf < 8; nf++) {
                int cg = n0 + wn * 64 + nf * 8 + 2 * lc;   // = 4j+g (even)
                float v0 = acc[mi][nf][0] + bias[cg];
                float v1 = acc[mi][nf][1] + bias[cg + 1];
                float v2 = acc[mi][nf][2] + bias[cg];
                float v3 = acc[mi][nf][3] + bias[cg + 1];
                float p0 = __shfl_xor_sync(0xffffffffu, v0, 1);
                float p1 = __shfl_xor_sync(0xffffffffu, v1, 1);
                float p2 = __shfl_xor_sync(0xffffffffu, v2, 1);
                float p3 = __shfl_xor_sync(0xffffffffu, v3, 1);
                if ((lane & 1) == 0) {
                    int j  = cg >> 2;
                    int r0 = rb + mi * 16, r1 = r0 + 8;
                    {
                        float i_ = fsig(v0), f_ = fsig(v1);
                        float g_ = ftanh(p0), o_ = fsig(p1);
                        float co = first ? 0.0f : O2[(size_t)r0 * ldo2 + j];
                        float cn = f_ * co + i_ * g_;
                        O2[(size_t)r0 * ldo2 + j] = cn;
                        O1[(size_t)r0 * ldo1 + j] = o_ * ftanh(cn);
                    }
                    {
                        float i_ = fsig(v2), f_ = fsig(v3);
                        float g_ = ftanh(p2), o_ = fsig(p3);
                        float co = first ? 0.0f : O2[(size_t)r1 * ldo2 + j];
                        float cn = f_ * co + i_ * g_;
                        O2[(size_t)r1 * ldo2 + j] = cn;
                        O1[(size_t)r1 * ldo1 + j] = o_ * ftanh(cn);
                    }
                }
            }
        }
    }
}

// ---------------------------------------------------------------------------
// Launch sequence (graph-capturable: kernel launches only)
// ---------------------------------------------------------------------------
extern "C" void kernel_launch(void* const* d_in, const int* in_sizes, int n_in,
                              void* d_out, int out_size)
{
    const float* x      = (const float*)d_in[0];
    const float* W_ih_e = (const float*)d_in[1];
    const float* W_hh_e = (const float*)d_in[2];
    const float* b_ih_e = (const float*)d_in[3];
    const float* b_hh_e = (const float*)d_in[4];
    const float* W_ih_d = (const float*)d_in[5];
    const float* W_hh_d = (const float*)d_in[6];
    const float* b_ih_d = (const float*)d_in[7];
    const float* b_hh_d = (const float*)d_in[8];
    const float* W_fc   = (const float*)d_in[9];
    const float* b_fc   = (const float*)d_in[10];
    const float* W_fcc  = (const float*)d_in[11];
    const float* b_fcc  = (const float*)d_in[12];
    const float* W_out  = (const float*)d_in[13];
    const float* b_out  = (const float*)d_in[14];
    float* out = (float*)d_out;

    float *h, *c, *hcat, *cd, *We, *Wd, *be, *bd;
    cudaGetSymbolAddress((void**)&h,    g_h);
    cudaGetSymbolAddress((void**)&c,    g_c);
    cudaGetSymbolAddress((void**)&hcat, g_hcat);
    cudaGetSymbolAddress((void**)&cd,   g_cd);
    cudaGetSymbolAddress((void**)&We,   g_We);
    cudaGetSymbolAddress((void**)&Wd,   g_Wd);
    cudaGetSymbolAddress((void**)&be,   g_be);
    cudaGetSymbolAddress((void**)&bd,   g_bd);

    const int SMEM_L = STAGES * (128 + 256) * SMS * 4;  // 165,888 B
    const int SMEM_B = STAGES * (128 + 128) * SMS * 4;  // 110,592 B
    const int SMEM_O = STAGES * (64 + 128) * SMS * 4;   //  82,944 B
    cudaFuncSetAttribute(gemm_k<128, 256, true>,  cudaFuncAttributeMaxDynamicSharedMemorySize, SMEM_L);
    cudaFuncSetAttribute(gemm_k<128, 128, false>, cudaFuncAttributeMaxDynamicSharedMemorySize, SMEM_B);
    cudaFuncSetAttribute(gemm_k<64, 128, false>,  cudaFuncAttributeMaxDynamicSharedMemorySize, SMEM_O);

    // ---- weight prep ----
    {
        long total = (long)G4 * KCAT;
        int blocks = (int)((total + 255) / 256);
        prep_w<<<blocks, 256>>>(W_hh_e, W_ih_e, b_ih_e, b_hh_e, We, be);
        prep_w<<<blocks, 256>>>(W_hh_d, W_ih_d, b_ih_d, b_hh_d, Wd, bd);
    }

    const dim3 gL(G4 / 256, BATCH / 128);   // (16, 8) — 128 CTAs
    const dim3 gB(HID / 128, BATCH / 128);  // (8, 8)
    const dim3 gO(OUTSZ / 128, BATCH / 64); // (1, 16)

    // ---- encoder: 96 fused GEMM+LSTM steps ----
    int p = 0;
    for (int t = 0; t < SEQ; t++) {
        gemm_k<128, 256, true><<<gL, 512, SMEM_L>>>(
            h + (size_t)p * BATCH * HID, HID,
            x + (size_t)t * INSZ, SEQ * INSZ,
            We, KCAT, be,
            h + (size_t)(1 - p) * BATCH * HID, HID,
            c, HID,
            (t == 0) ? 32 : 0, 36, (t == 0) ? 1 : 0);
        p ^= 1;
    }
    float* h_fin = h + (size_t)p * BATCH * HID;

    // ---- bridge ----
    float* hc0 = hcat;
    float* hc1 = hcat + (size_t)BATCH * KCAT;
    gemm_k<128, 128, false><<<gB, 256, SMEM_B>>>(
        h_fin, HID, nullptr, 0, W_fc, HID, b_fc,
        hc0, KCAT, nullptr, 0, 0, 32, 0);
    gemm_k<128, 128, false><<<gB, 256, SMEM_B>>>(
        h_fin, HID, nullptr, 0, W_fcc, HID, b_fcc,
        cd, HID, nullptr, 0, 0, 32, 0);

    // ---- decoder: 24 steps ----
    int q = 0;
    for (int t = 0; t < HORIZON; t++) {
        float* src = (q == 0) ? hc0 : hc1;
        float* dst = (q == 0) ? hc1 : hc0;
        gemm_k<128, 256, true><<<gL, 512, SMEM_L>>>(
            src, KCAT, src + HID, KCAT,
            Wd, KCAT, bd,
            dst, KCAT,
            cd, HID,
            0, (t == 0) ? 32 : 36, 0);
        gemm_k<64, 128, false><<<gO, 128, SMEM_O>>>(
            dst, KCAT, nullptr, 0, W_out, HID, b_out,
            out + (size_t)t * OUTSZ, HORIZON * OUTSZ,
            dst + HID, KCAT, 0, 32, 0);
        q ^= 1;
    }
}